// round 15
// baseline (speedup 1.0000x reference)
#include <cuda_runtime.h>
#include <cstdint>

#define TPB    768
#define NW     24
#define NPG    150      // nodes per graph
#define HALF   75       // rows per CTA (2 CTAs per graph)
#define HID    64
#define CL     25
#define CP     26       // padded cluster stride
#define NFEAT  128
#define NCLS   10
#define NTOT   9600
#define MAXC   48       // max neighbors+self per row (multiple of 4 for int4 reads)
#define XTS    84       // xt row stride (floats): 16B-aligned tiles, bounded conflicts

// ---- shared memory layout (float offsets) ----
#define OFF_COLS  0                          // 75*48 ints = 3600
#define OFF_RC    (OFF_COLS + HALF*MAXC)     // 80 ints (per-row nnz count)
#define OFF_DIS   (OFF_RC + 80)              // 80 floats
#define OFF_BUFA  (OFF_DIS + 80)             // 152*64 = 9728 (pad rows zero; xt overlay in B)
#define OFF_BUFB  (OFF_BUFA + 152*HID)       // 152*64 = 9728 (xt overflow in B)
#define OFF_SMT   (OFF_BUFB + 152*HID)       // 152*26 = 3952 (scratch with ST/ZP)
#define OFF_ST    (OFF_SMT + 152*CP)         // 25*152 = 3800 (S transposed, full)
#define OFF_ZP    (OFF_ST + CL*152)          // 25*64 = 1600
#define OFF_AP    (OFF_ZP + CL*HID)          // 25*26+6 = 656
#define OFF_DISP  (OFF_AP + CL*CP + 6)       // 32
#define OFF_GV    (OFF_DISP + 32)            // 64
#define SMEM_FLOATS (OFF_GV + 64)

#define CLUSTER_SYNC() do { \
    asm volatile("barrier.cluster.arrive.aligned;" ::: "memory"); \
    asm volatile("barrier.cluster.wait.aligned;"   ::: "memory"); } while (0)

__device__ __forceinline__ unsigned int smem_u32(const void* p) {
    unsigned int a;
    asm("{ .reg .u64 t; cvta.to.shared.u64 t, %1; cvt.u32.u64 %0, t; }"
        : "=r"(a) : "l"(p));
    return a;
}
__device__ __forceinline__ void st_rem(unsigned int addr, float v) {
    asm volatile("st.shared::cluster.f32 [%0], %1;" :: "r"(addr), "f"(v));
}
__device__ __forceinline__ void st_rem2(unsigned int addr, float vx, float vy) {
    unsigned long long p;
    asm("mov.b64 %0, {%1,%2};" : "=l"(p) : "f"(vx), "f"(vy));
    asm volatile("st.shared::cluster.b64 [%0], %1;" :: "r"(addr), "l"(p));
}
// acc(f32x2) += (a,a) * b(f32x2)
__device__ __forceinline__ void fma2(unsigned long long& acc, float a, unsigned long long b) {
    asm("{\n\t.reg .b64 t;\n\tmov.b64 t, {%1, %1};\n\tfma.rn.f32x2 %0, t, %2, %0;\n\t}"
        : "+l"(acc) : "f"(a), "l"(b));
}
__device__ __forceinline__ float2 unpack2(unsigned long long v) {
    float2 r;
    asm("mov.b64 {%0, %1}, %2;" : "=f"(r.x), "=f"(r.y) : "l"(v));
    return r;
}

// Sparse aggregate: out[i][h] = act(dis[i]*sum_{c in cols[i]} in[c][h] + bias[h]).
// 15 warps x 5 contiguous rows, per-row early-exit predication.
template<bool RELU, bool REMOTE_ALL>
__device__ __forceinline__ void agg_sp(float* sm, const int* COLS, const int* RCNT,
                                       const float* DISL, int in_off, int out_off,
                                       const float* __restrict__ bias,
                                       int tid, int row0, unsigned int rbase, int nrem)
{
    const int lane = tid & 31, w = tid >> 5;
    if (w >= 15) return;
    const int l0 = w * 5;
    const int rb = l0 * MAXC;
    int cnt[5];
#pragma unroll
    for (int r = 0; r < 5; ++r) cnt[r] = RCNT[l0 + r];
    int kmax = cnt[0];
#pragma unroll
    for (int r = 1; r < 5; ++r) kmax = max(kmax, cnt[r]);
    float2 acc[5];
#pragma unroll
    for (int r = 0; r < 5; ++r) acc[r] = make_float2(0.f, 0.f);
    const float2* IN2 = (const float2*)(sm + in_off);
    for (int k = 0; k < kmax; k += 4) {
#pragma unroll
        for (int r = 0; r < 5; ++r) {
            if (k < cnt[r]) {
                int4 c4 = *(const int4*)(COLS + rb + r * MAXC + k);
                float2 v;
                v = IN2[c4.x * 32 + lane]; acc[r].x += v.x; acc[r].y += v.y;
                v = IN2[c4.y * 32 + lane]; acc[r].x += v.x; acc[r].y += v.y;
                v = IN2[c4.z * 32 + lane]; acc[r].x += v.x; acc[r].y += v.y;
                v = IN2[c4.w * 32 + lane]; acc[r].x += v.x; acc[r].y += v.y;
            }
        }
    }
    float2 bv = *(const float2*)(bias + 2 * lane);
#pragma unroll
    for (int r = 0; r < 5; ++r) {
        int l = l0 + r;
        float d = DISL[l];
        float vx = d * acc[r].x + bv.x;
        float vy = d * acc[r].y + bv.y;
        if (RELU) { vx = fmaxf(vx, 0.f); vy = fmaxf(vy, 0.f); }
        int fo = out_off + (row0 + l) * HID + 2 * lane;
        *(float2*)(sm + fo) = make_float2(vx, vy);
        if (REMOTE_ALL || l < nrem)
            st_rem2(rbase + 4u * (unsigned int)fo, vx, vy);
    }
}

__global__ void __launch_bounds__(TPB, 1) __cluster_dims__(2, 1, 1)
gcn_diffpool(const float* __restrict__ x,  const float* __restrict__ a,
             const float* __restrict__ W1, const float* __restrict__ b1,
             const float* __restrict__ W2, const float* __restrict__ b2,
             const float* __restrict__ Wa, const float* __restrict__ ba,
             const float* __restrict__ Wp, const float* __restrict__ bp,
             const float* __restrict__ Wc, const float* __restrict__ bc,
             float* __restrict__ out)
{
    extern __shared__ float sm[];
    int*   COLS = (int*)(sm + OFF_COLS);
    int*   RCNT = (int*)(sm + OFF_RC);
    float* DISL = sm + OFF_DIS;
    float* BA   = sm + OFF_BUFA;
    float* BB   = sm + OFF_BUFB;
    float* SMT  = sm + OFF_SMT;
    float* ST   = sm + OFF_ST;
    float* ZP   = sm + OFF_ZP;
    float* AP   = sm + OFF_AP;
    float* DISP = sm + OFF_DISP;
    float* GV   = sm + OFF_GV;

    const int tid  = threadIdx.x;
    const int g    = blockIdx.x >> 1;
    const int base = g * NPG;
    const int lane = tid & 31;
    const int w    = tid >> 5;              // 0..23
    const int c32  = lane;

    unsigned int rank;
    asm("mov.u32 %0, %%cluster_ctarank;" : "=r"(rank));
    const int row0 = (int)rank * HALF;
    unsigned int rbase;
    {
        unsigned int lbase = smem_u32(sm);
        unsigned int peer = rank ^ 1u;
        asm("mapa.shared::cluster.u32 %0, %1, %2;" : "=r"(rbase) : "r"(lbase), "r"(rbase), "r"(peer));
    }
    // (re-issue mapa cleanly — above form keeps operands explicit)
    {
        unsigned int lbase = smem_u32(sm);
        unsigned int peer = rank ^ 1u;
        asm("mapa.shared::cluster.u32 %0, %1, %2;" : "=r"(rbase) : "r"(lbase), "r"(peer));
    }

    // ---------- Stage: xt[k][row] transposed (stride XTS, overlaying BUFA/BUFB) + W1 ----------
    {
        float* xt  = BA;            // 128*84 = 10752 floats (BUFA + 1024 of BUFB)
        float* wst = sm + OFF_SMT;  // 8192 floats (SMT+ST+440 of ZP)
        for (int idx = tid; idx < HALF * NFEAT; idx += TPB) {
            int row = idx >> 7, col = idx & 127;
            xt[col * XTS + row] = x[(size_t)(base + row0 + row) * NFEAT + col];
        }
        for (int idx = tid; idx < NFEAT * HID; idx += TPB) wst[idx] = W1[idx];
        // zero xt pad rows 75..83 so warp 9's extra lanes read finite values
        for (int k = tid; k < NFEAT; k += TPB) {
#pragma unroll
            for (int r = HALF; r < XTS; ++r) xt[k * XTS + r] = 0.f;
        }
    }
    __syncthreads();

    // ---------- Parallel: Phase B matmul (warps 0-9) ∥ Phase A CSR build (warps 10-23) ----------
    unsigned long long bacc[8] = {0ull,0ull,0ull,0ull,0ull,0ull,0ull,0ull};
    if (w < 10) {
        const float* xt  = BA;
        const float* wst = sm + OFF_SMT;
        const int r0 = w * 8;
        for (int k = 0; k < NFEAT; ++k) {
            float4 xa = *(const float4*)(xt + k * XTS + r0);
            float4 xb = *(const float4*)(xt + k * XTS + r0 + 4);
            unsigned long long wk = *(const unsigned long long*)(wst + k * HID + 2 * lane);
            fma2(bacc[0], xa.x, wk);
            fma2(bacc[1], xa.y, wk);
            fma2(bacc[2], xa.z, wk);
            fma2(bacc[3], xa.w, wk);
            fma2(bacc[4], xb.x, wk);
            fma2(bacc[5], xb.y, wk);
            fma2(bacc[6], xb.z, wk);
            fma2(bacc[7], xb.w, wk);
        }
    } else {
        // Phase A: CSR (neighbors + self) + degrees; warps 10-23, 6 row-slots each
        const int aw = w - 10;
        float vv[6][5];
#pragma unroll
        for (int r = 0; r < 6; ++r) {
            int l = min(aw * 6 + r, HALF - 1);
            const float* arow = a + (size_t)(base + row0 + l) * NTOT + base;
#pragma unroll
            for (int ch = 0; ch < 5; ++ch) {
                int col = ch * 32 + lane;
                vv[r][ch] = (col < NPG) ? arow[col] : 0.f;
            }
        }
#pragma unroll
        for (int r = 0; r < 6; ++r) {
            int l = aw * 6 + r;
            if (l < HALF) {
                int self = row0 + l;
                int cnt = 0;
#pragma unroll
                for (int ch = 0; ch < 5; ++ch) {
                    int col = ch * 32 + lane;
                    bool nz = (col < NPG) && (vv[r][ch] != 0.f || col == self);
                    unsigned m = __ballot_sync(0xffffffffu, nz);
                    if (nz) {
                        int p = cnt + __popc(m & ((1u << lane) - 1u));
                        if (p < MAXC) COLS[l * MAXC + p] = col;
                    }
                    cnt += __popc(m);
                }
                int cc = min(cnt, MAXC);
                for (int kk = cc + lane; kk < MAXC; kk += 32) COLS[l * MAXC + kk] = NPG;
                if (lane == 0) { DISL[l] = rsqrtf((float)cnt); RCNT[l] = cc; }
            }
        }
    }
    __syncthreads();   // DISL ready; all xt reads done

    // ---------- B epilogue: apply dis, store BA local + peer; zero pads ----------
    if (w < 10) {
        const int r0 = w * 8;
#pragma unroll
        for (int r = 0; r < 8; ++r) {
            int l = r0 + r;
            if (l < HALF) {
                float2 m = unpack2(bacc[r]);
                float d = DISL[l];
                float vx = m.x * d, vy = m.y * d;
                int fo = OFF_BUFA + (row0 + l) * HID + 2 * lane;
                *(float2*)(sm + fo) = make_float2(vx, vy);
                st_rem2(rbase + 4u * (unsigned int)fo, vx, vy);
            }
        }
    }
    if (tid < 128) { BA[NPG * HID + tid] = 0.f; BB[NPG * HID + tid] = 0.f; }
    CLUSTER_SYNC();

    // ---------- Phase C1 (warps 0-14, local) ∥ stage W2 (warps 15-23) ----------
    agg_sp<true, false>(sm, COLS, RCNT, DISL, OFF_BUFA, OFF_BUFB, b1, tid, row0, rbase, 0);
    if (w >= 15) {
        float* wfl = sm + OFF_SMT;   // W2 64*64 = 4096 (scratch free: B done)
        for (int idx = tid - 480; idx < HID * HID; idx += 288) wfl[idx] = W2[idx];
    }
    __syncthreads();

    // ---------- Phase D: BA[j][h] = dis[j]*(Z1[j].W2[:,h]); 15 warps x 5 rows ----------
    if (w < 15) {
        float* wfl = sm + OFF_SMT;
        const int r0 = w * 5;
        unsigned long long acc[5] = {0ull, 0ull, 0ull, 0ull, 0ull};
        for (int k = 0; k < HID; k += 4) {
            unsigned long long w0 = *(const unsigned long long*)(wfl + (k + 0) * HID + 2 * lane);
            unsigned long long w1 = *(const unsigned long long*)(wfl + (k + 1) * HID + 2 * lane);
            unsigned long long w2 = *(const unsigned long long*)(wfl + (k + 2) * HID + 2 * lane);
            unsigned long long w3 = *(const unsigned long long*)(wfl + (k + 3) * HID + 2 * lane);
#pragma unroll
            for (int r = 0; r < 5; ++r) {
                float4 zv = *(const float4*)(BB + (row0 + r0 + r) * HID + k);
                fma2(acc[r], zv.x, w0);
                fma2(acc[r], zv.y, w1);
                fma2(acc[r], zv.z, w2);
                fma2(acc[r], zv.w, w3);
            }
        }
#pragma unroll
        for (int r = 0; r < 5; ++r) {
            int l = r0 + r;
            float2 m = unpack2(acc[r]);
            float d = DISL[l];
            float vx = m.x * d, vy = m.y * d;
            int fo = OFF_BUFA + (row0 + l) * HID + 2 * lane;
            *(float2*)(sm + fo) = make_float2(vx, vy);
            st_rem2(rbase + 4u * (unsigned int)fo, vx, vy);
        }
    }
    CLUSTER_SYNC();

    // ---------- Phase C2 (warps 0-14, local; rank1 mirrors row 75 only) ∥ stage Wa + pads ----------
    agg_sp<true, false>(sm, COLS, RCNT, DISL, OFF_BUFA, OFF_BUFB, b2, tid, row0, rbase,
                        (rank == 1) ? 1 : 0);
    if (w >= 15) {
        int t = tid - 480;
        for (int idx = t; idx < HID * CL; idx += 288) ZP[idx] = Wa[idx];
        if (t < 2 * CP) SMT[NPG * CP + t] = 0.f;
        if (t < 2 * CL) ST[(t >> 1) * 152 + NPG + (t & 1)] = 0.f;
    }
    __syncthreads();

    // ---------- Phase E: tmpS[j][c] = dis[j]*(Z2[j].Wa[:,c]); 15 warps x 5 rows -> SMT both ----------
    if (w < 15) {
        const int cidx = min(c32, CL - 1);
        const int l0 = w * 5;
        float acc[5] = {0.f, 0.f, 0.f, 0.f, 0.f};
        for (int k = 0; k < HID; k += 4) {
            float w0 = ZP[(k + 0) * CL + cidx];
            float w1 = ZP[(k + 1) * CL + cidx];
            float w2 = ZP[(k + 2) * CL + cidx];
            float w3 = ZP[(k + 3) * CL + cidx];
#pragma unroll
            for (int r = 0; r < 5; ++r) {
                float4 zv = *(const float4*)(BB + (row0 + l0 + r) * HID + k);
                acc[r] += zv.x * w0 + zv.y * w1 + zv.z * w2 + zv.w * w3;
            }
        }
        if (c32 < CL) {
#pragma unroll
            for (int r = 0; r < 5; ++r) {
                int l = l0 + r;
                float v = acc[r] * DISL[l];
                int fo = OFF_SMT + (row0 + l) * CP + c32;
                sm[fo] = v;
                st_rem(rbase + 4u * (unsigned int)fo, v);
            }
        }
    }
    CLUSTER_SYNC();

    // ---------- Phase F+G: logits (sparse, predicated) + warp softmax -> S into BA both + ST both ----------
    if (w < 15) {
        const int cidx = min(c32, CL - 1);
        const int l0 = w * 5;
        const int rb = l0 * MAXC;
        int cnt[5];
#pragma unroll
        for (int r = 0; r < 5; ++r) cnt[r] = RCNT[l0 + r];
        int kmax = cnt[0];
#pragma unroll
        for (int r = 1; r < 5; ++r) kmax = max(kmax, cnt[r]);
        float acc[5] = {0.f, 0.f, 0.f, 0.f, 0.f};
        for (int k = 0; k < kmax; k += 4) {
#pragma unroll
            for (int r = 0; r < 5; ++r) {
                if (k < cnt[r]) {
                    int4 c4 = *(const int4*)(COLS + rb + r * MAXC + k);
                    acc[r] += SMT[c4.x * CP + c32] + SMT[c4.y * CP + c32]
                            + SMT[c4.z * CP + c32] + SMT[c4.w * CP + c32];
                }
            }
        }
        float bac = ba[cidx];
#pragma unroll
        for (int r = 0; r < 5; ++r) {
            int l = l0 + r;
            float logit = DISL[l] * acc[r] + bac;
            float mv = (c32 < CL) ? logit : -3.0e38f;
#pragma unroll
            for (int off = 16; off; off >>= 1)
                mv = fmaxf(mv, __shfl_xor_sync(0xffffffffu, mv, off));
            float e = (c32 < CL) ? expf(logit - mv) : 0.f;
            float s = e;
#pragma unroll
            for (int off = 16; off; off >>= 1)
                s += __shfl_xor_sync(0xffffffffu, s, off);
            float sv = e * (1.f / s);
            if (c32 < CL) {
                int gi = row0 + l;
                int fo = OFF_BUFA + gi * HID + c32;
                sm[fo] = sv;
                st_rem(rbase + 4u * (unsigned int)fo, sv);
                int ft = OFF_ST + c32 * 152 + gi;
                sm[ft] = sv;
                st_rem(rbase + 4u * (unsigned int)ft, sv);
            }
        }
    }
    CLUSTER_SYNC();

    // ---------- Phase I (warps 0-14) ∥ Phase H-partial (warps 15-23, BOTH ranks) ----------
    float2 hacc[3];
    hacc[0] = hacc[1] = hacc[2] = make_float2(0.f, 0.f);
    const int wh = w - 15;
    const int cb = wh * 3;
    if (w < 15) {
        const int l0 = w * 5;
        const int rb = l0 * MAXC;
        int cnt[5];
#pragma unroll
        for (int r = 0; r < 5; ++r) cnt[r] = RCNT[l0 + r];
        int kmax = cnt[0];
#pragma unroll
        for (int r = 1; r < 5; ++r) kmax = max(kmax, cnt[r]);
        float acc[5] = {0.f, 0.f, 0.f, 0.f, 0.f};
        for (int k = 0; k < kmax; k += 4) {
#pragma unroll
            for (int r = 0; r < 5; ++r) {
                if (k < cnt[r]) {
                    int4 c4 = *(const int4*)(COLS + rb + r * MAXC + k);
                    acc[r] += BA[c4.x * HID + c32] + BA[c4.y * HID + c32]
                            + BA[c4.z * HID + c32] + BA[c4.w * HID + c32];
                }
            }
        }
        if (c32 < CL) {
#pragma unroll
            for (int r = 0; r < 5; ++r) {
                int gi = row0 + l0 + r;
                float v = acc[r] - BA[gi * HID + c32];
                int fo = OFF_SMT + gi * CP + c32;
                sm[fo] = v;
                st_rem(rbase + 4u * (unsigned int)fo, v);
            }
        }
    } else {
        // H-partial: rank0 j=0..75, rank1 j=76..151 (rows 150/151 zero)
        const int j0 = (rank == 0) ? 0 : 76;
        for (int jj = 0; jj < 76; jj += 4) {
            int j = j0 + jj;
            float2 z0 = *(const float2*)(BB + (j + 0) * HID + 2 * lane);
            float2 z1 = *(const float2*)(BB + (j + 1) * HID + 2 * lane);
            float2 z2 = *(const float2*)(BB + (j + 2) * HID + 2 * lane);
            float2 z3 = *(const float2*)(BB + (j + 3) * HID + 2 * lane);
#pragma unroll
            for (int o = 0; o < 3; ++o) {
                int c = cb + o;
                if (c < CL) {
                    float4 s = *(const float4*)(ST + c * 152 + j);
                    hacc[o].x += s.x * z0.x + s.y * z1.x + s.z * z2.x + s.w * z3.x;
                    hacc[o].y += s.x * z0.y + s.y * z1.y + s.z * z2.y + s.w * z3.y;
                }
            }
        }
#pragma unroll
        for (int o = 0; o < 3; ++o) {
            int c = cb + o;
            if (c < CL) {
                int fo = OFF_ZP + c * HID + 2 * lane;
                st_rem2(rbase + 4u * (unsigned int)fo, hacc[o].x, hacc[o].y);
            }
        }
    }
    CLUSTER_SYNC();

    // ---------- H-add (warps 15-23): ZP = peer partial + own partial ----------
    if (w >= 15) {
#pragma unroll
        for (int o = 0; o < 3; ++o) {
            int c = cb + o;
            if (c < CL) {
                int fo = OFF_ZP + c * HID + 2 * lane;
                float2 p = *(const float2*)(sm + fo);
                *(float2*)(sm + fo) = make_float2(p.x + hacc[o].x, p.y + hacc[o].y);
            }
        }
    }
    // ---------- Phase J (redundant, local) ∥ stage Wp -> BB ----------
    if (tid < CL * CL) {
        int cc = tid / CL, d = tid - cc * CL;
        float acc = 0.f;
        for (int j = 0; j < 152; j += 4) {
            float4 s = *(const float4*)(ST + cc * 152 + j);
            acc += s.x * SMT[(j + 0) * CP + d] + s.y * SMT[(j + 1) * CP + d]
                 + s.z * SMT[(j + 2) * CP + d] + s.w * SMT[(j + 3) * CP + d];
        }
        AP[cc * CP + d] = acc;
    }
    if (tid >= 640) {
        for (int idx = tid - 640; idx < HID * HID; idx += 128) BB[idx] = Wp[idx];
    }
    __syncthreads();

    // ---------- Phase K: pooled degrees ----------
    if (tid < CL) {
        float s = 1.0f;
        for (int d = 0; d < CL; ++d) s += AP[tid * CP + d];
        DISP[tid] = rsqrtf(fmaxf(s, 1e-12f));
    }
    __syncthreads();

    // ---------- Phase L: BA[c][h] = disp[c]*(Zp[c].Wp[:,h]) ----------
    for (int idx = tid; idx < CL * HID; idx += TPB) {
        int cc = idx >> 6, hh = idx & 63;
        float acc = 0.f;
        for (int k = 0; k < HID; k += 4) {
            float4 zv = *(const float4*)(ZP + cc * HID + k);
            acc += zv.x * BB[(k + 0) * HID + hh] + zv.y * BB[(k + 1) * HID + hh]
                 + zv.z * BB[(k + 2) * HID + hh] + zv.w * BB[(k + 3) * HID + hh];
        }
        BA[cc * HID + hh] = acc * DISP[cc];
    }
    __syncthreads();

    // ---------- Phase M: Hp = relu(disp[i]*sum_c (Ap+I)[i][c]*BA[c][h] + bp) -> ZP ----------
    for (int idx = tid; idx < CL * HID; idx += TPB) {
        int i = idx >> 6, hh = idx & 63;
        float acc = 0.f;
#pragma unroll
        for (int cc = 0; cc < CL; ++cc) {
            float av = AP[i * CP + cc] + ((i == cc) ? 1.f : 0.f);
            acc += av * BA[cc * HID + hh];
        }
        ZP[i * HID + hh] = fmaxf(DISP[i] * acc + bp[hh], 0.f);
    }
    __syncthreads();

    // ---------- Phase N: readout ----------
    if (tid < HID) {
        float s = 0.f;
#pragma unroll
        for (int i = 0; i < CL; ++i) s += ZP[i * HID + tid];
        GV[tid] = s;
    }
    __syncthreads();

    // ---------- Phase O: logits (rank 0 writes) ----------
    if (rank == 0 && tid < NCLS) {
        float acc = bc[tid];
#pragma unroll
        for (int k = 0; k < HID; ++k) acc += GV[k] * Wc[k * NCLS + tid];
        out[g * NCLS + tid] = acc;
    }
}

extern "C" void kernel_launch(void* const* d_in, const int* in_sizes, int n_in,
                              void* d_out, int out_size)
{
    const float* x  = (const float*)d_in[0];
    const float* a  = (const float*)d_in[1];
    const float* W1 = (const float*)d_in[4];
    const float* b1 = (const float*)d_in[5];
    const float* W2 = (const float*)d_in[6];
    const float* b2 = (const float*)d_in[7];
    const float* Wa = (const float*)d_in[8];
    const float* ba = (const float*)d_in[9];
    const float* Wp = (const float*)d_in[10];
    const float* bp = (const float*)d_in[11];
    const float* Wc = (const float*)d_in[12];
    const float* bc = (const float*)d_in[13];
    float* out = (float*)d_out;

    int B = out_size / NCLS;   // 64 graphs
    size_t smem = (size_t)SMEM_FLOATS * sizeof(float);
    cudaFuncSetAttribute(gcn_diffpool, cudaFuncAttributeMaxDynamicSharedMemorySize, (int)smem);
    gcn_diffpool<<<B * 2, TPB, smem>>>(x, a, W1, b1, W2, b2, Wa, ba, Wp, bp, Wc, bc, out);
}